// round 4
// baseline (speedup 1.0000x reference)
#include <cuda_runtime.h>
#include <cstdint>

#define BB 32
#define TT 256
#define DD 512
#define PP 20
#define EPSV 1e-12f

// ---------------- scratch (__device__ globals; no cudaMalloc allowed) ------
__device__ float g_nbn [BB * TT * DD];            // normalized b, [b][t][d]
__device__ float g_nbnT[BB * DD * TT];            // normalized b, [b][d][t]
__device__ float g_nanT[BB * DD * TT];            // normalized a, [b][d][t]
__device__ float g_alphaT[(size_t)BB * DD * DD];  // [b][e][d]
__device__ float g_invcol[BB * DD];               // per (b,e)
__device__ float g_hmean[BB * TT * DD];           // [b][t][e]

__device__ __forceinline__ uint32_t smem_u32(const void* p) {
    return (uint32_t)__cvta_generic_to_shared(p);
}

// ---------------------------------------------------------------------------
// Kernel 1: row l2-normalize + transpose.  Block = 256 thr, tile = 16 t-rows.
// which=0: a -> g_nanT only.  which=1: b -> g_nbn + g_nbnT.
// ---------------------------------------------------------------------------
__global__ void __launch_bounds__(256) k_normT(const float* __restrict__ a,
                                               const float* __restrict__ b) {
    __shared__ float s[16 * 513];
    __shared__ float sinv[16];
    int which = blockIdx.z;
    int bb = blockIdx.y;
    int t0 = blockIdx.x * 16;
    const float* src = (which ? b : a) + ((size_t)bb * TT + t0) * DD;
    int tid = threadIdx.x;

#pragma unroll
    for (int i = 0; i < 8; i++) {
        int idx = tid + i * 256;
        int r = idx >> 7, c4 = idx & 127;
        float4 v = *(const float4*)(src + (size_t)r * DD + c4 * 4);
        float* sr = s + r * 513 + c4 * 4;
        sr[0] = v.x; sr[1] = v.y; sr[2] = v.z; sr[3] = v.w;
    }
    __syncthreads();

    int wid = tid >> 5, lid = tid & 31;
#pragma unroll
    for (int rr = 0; rr < 2; rr++) {
        int r = wid * 2 + rr;
        float ss = 0.f;
#pragma unroll
        for (int j = 0; j < 16; j++) { float v = s[r * 513 + lid + 32 * j]; ss += v * v; }
#pragma unroll
        for (int o = 16; o > 0; o >>= 1) ss += __shfl_xor_sync(0xffffffffu, ss, o);
        if (lid == 0) sinv[r] = rsqrtf(fmaxf(ss, EPSV));
    }
    __syncthreads();

    // transposed write: nT[d][t0+j]
    float* dstT = (which ? g_nbnT : g_nanT) + (size_t)bb * DD * TT;
#pragma unroll
    for (int i = 0; i < 8; i++) {
        int idx = tid + i * 256;          // float4 units over 512 x 16
        int d = idx >> 2, jq = (idx & 3) * 4;
        float4 o;
        o.x = s[(jq + 0) * 513 + d] * sinv[jq + 0];
        o.y = s[(jq + 1) * 513 + d] * sinv[jq + 1];
        o.z = s[(jq + 2) * 513 + d] * sinv[jq + 2];
        o.w = s[(jq + 3) * 513 + d] * sinv[jq + 3];
        *(float4*)(dstT + (size_t)d * TT + t0 + jq) = o;
    }
    if (which) {
        float* dst = g_nbn + ((size_t)bb * TT + t0) * DD;
#pragma unroll
        for (int i = 0; i < 8; i++) {
            int idx = tid + i * 256;
            int r = idx >> 7, c4 = idx & 127;
            float inv = sinv[r];
            float* sr = s + r * 513 + c4 * 4;
            float4 o = make_float4(sr[0] * inv, sr[1] * inv, sr[2] * inv, sr[3] * inv);
            *(float4*)(dst + (size_t)r * DD + c4 * 4) = o;
        }
    }
}

// ---------------------------------------------------------------------------
// tf32 mma.sync GEMM with 3-stage cp.async pipeline.
// D[m,n] = sum_k A[m,k]*B[n,k], both K-major. CTA tile 128x128, K-chunk 16.
// fp32 fed raw to tf32 mma (hw truncation; error << 1e-3 budget).
// smem: 3 stages x (A 128x16 + B 128x16) = 48KB, XOR-group swizzle.
// Store transposed: C[n*512 + m], optional per-m scale.
// ---------------------------------------------------------------------------
__device__ __forceinline__ int sw_addr(int r, int c) {
    // 16 words per row; swizzle float4-group by row low bits
    return r * 16 + ((((c >> 2) ^ r) & 3) << 2) + (c & 3);
}

__global__ void __launch_bounds__(256, 2) k_gemm_mma(
    const float* __restrict__ Ag, int lda, size_t strideA,
    const float* __restrict__ Bg, int ldb, size_t strideB,
    float* __restrict__ Cg, size_t strideC,
    const float* __restrict__ scale,   // [BB*DD] indexed by m, or null
    int Ktot) {
    __shared__ __align__(16) uint32_t sm[3 * 4096];  // 48KB

    int b = blockIdx.z;
    int m0 = blockIdx.x * 128, n0 = blockIdx.y * 128;
    const float* A  = Ag + (size_t)b * strideA + (size_t)m0 * lda;
    const float* Bp = Bg + (size_t)b * strideB + (size_t)n0 * ldb;

    int tid = threadIdx.x, lane = tid & 31, wid = tid >> 5;
    int wm = wid & 1, wn = wid >> 1;   // 2 x 4 warp grid
    uint32_t smbase = smem_u32(sm);

    float acc[4][4][4];
#pragma unroll
    for (int i = 0; i < 4; i++)
#pragma unroll
        for (int j = 0; j < 4; j++)
#pragma unroll
            for (int k = 0; k < 4; k++) acc[i][j][k] = 0.f;

    int nkt = Ktot / 16;

    // cp.async one K-chunk into stage kt%3
    auto issue_chunk = [&](int kt) {
        uint32_t base = smbase + (uint32_t)(kt % 3) * 4096u * 4u;
        int k0 = kt * 16;
#pragma unroll
        for (int i = 0; i < 2; i++) {
            int idx = tid + i * 256;
            int r = idx >> 2, c4 = idx & 3;
            uint32_t off = (uint32_t)(r * 16 + (((c4 ^ r) & 3) << 2)) * 4u;
            const float* srcA = A + (size_t)r * lda + k0 + c4 * 4;
            asm volatile("cp.async.cg.shared.global [%0], [%1], 16;"
                         :: "r"(base + off), "l"(srcA));
            const float* srcB = Bp + (size_t)r * ldb + k0 + c4 * 4;
            asm volatile("cp.async.cg.shared.global [%0], [%1], 16;"
                         :: "r"(base + 2048u * 4u + off), "l"(srcB));
        }
        asm volatile("cp.async.commit_group;");
    };

    issue_chunk(0);
    issue_chunk(1);

    for (int kt = 0; kt < nkt; kt++) {
        asm volatile("cp.async.wait_group 1;" ::: "memory");
        __syncthreads();
        if (kt + 2 < nkt) issue_chunk(kt + 2);

        const uint32_t* sA = sm + (kt % 3) * 4096;
        const uint32_t* sB = sA + 2048;

#pragma unroll
        for (int ks = 0; ks < 2; ks++) {
            int c_lo = ks * 8 + (lane & 3);
            int c_hi = c_lo + 4;
            uint32_t af[4][4], bf[4][2];
#pragma unroll
            for (int mt = 0; mt < 4; mt++) {
                int r = wm * 64 + mt * 16 + (lane >> 2);
                af[mt][0] = sA[sw_addr(r, c_lo)];
                af[mt][1] = sA[sw_addr(r + 8, c_lo)];
                af[mt][2] = sA[sw_addr(r, c_hi)];
                af[mt][3] = sA[sw_addr(r + 8, c_hi)];
            }
#pragma unroll
            for (int nt = 0; nt < 4; nt++) {
                int r = wn * 32 + nt * 8 + (lane >> 2);
                bf[nt][0] = sB[sw_addr(r, c_lo)];
                bf[nt][1] = sB[sw_addr(r, c_hi)];
            }
#pragma unroll
            for (int mt = 0; mt < 4; mt++)
#pragma unroll
                for (int nt = 0; nt < 4; nt++) {
                    asm volatile(
                        "mma.sync.aligned.m16n8k8.row.col.f32.tf32.tf32.f32 "
                        "{%0,%1,%2,%3}, {%4,%5,%6,%7}, {%8,%9}, {%0,%1,%2,%3};"
                        : "+f"(acc[mt][nt][0]), "+f"(acc[mt][nt][1]),
                          "+f"(acc[mt][nt][2]), "+f"(acc[mt][nt][3])
                        : "r"(af[mt][0]), "r"(af[mt][1]),
                          "r"(af[mt][2]), "r"(af[mt][3]),
                          "r"(bf[nt][0]), "r"(bf[nt][1]));
                }
        }
        __syncthreads();
    }

    // ---- epilogue: transposed store C[n*512 + m], optional scale[m] ----
    float* Cb = Cg + (size_t)b * strideC;
    const float* scb = scale ? (scale + (size_t)b * DD) : nullptr;
#pragma unroll
    for (int mt = 0; mt < 4; mt++) {
        int r0 = m0 + wm * 64 + mt * 16 + (lane >> 2);
        float sc0 = scb ? scb[r0] : 1.0f;
        float sc1 = scb ? scb[r0 + 8] : 1.0f;
#pragma unroll
        for (int nt = 0; nt < 4; nt++) {
            int c0 = n0 + wn * 32 + nt * 8 + (lane & 3) * 2;
            Cb[(size_t)c0 * 512 + r0]           = acc[mt][nt][0] * sc0;
            Cb[(size_t)(c0 + 1) * 512 + r0]     = acc[mt][nt][1] * sc0;
            Cb[(size_t)c0 * 512 + r0 + 8]       = acc[mt][nt][2] * sc1;
            Cb[(size_t)(c0 + 1) * 512 + r0 + 8] = acc[mt][nt][3] * sc1;
        }
    }
}

// ---------------------------------------------------------------------------
// Column norms of alpha (= row norms of alphaT). One warp per (b,e).
// ---------------------------------------------------------------------------
__global__ void __launch_bounds__(256) k_colnorm() {
    int gw = (blockIdx.x * blockDim.x + threadIdx.x) >> 5;
    int lane = threadIdx.x & 31;
    if (gw >= BB * DD) return;
    const float4* r4 = (const float4*)(g_alphaT + (size_t)gw * DD);
    float ss = 0.f;
#pragma unroll
    for (int i = 0; i < 4; i++) {
        float4 v = r4[lane + 32 * i];
        ss += v.x * v.x + v.y * v.y + v.z * v.z + v.w * v.w;
    }
#pragma unroll
    for (int o = 16; o > 0; o >>= 1) ss += __shfl_xor_sync(0xffffffffu, ss, o);
    if (lane == 0) g_invcol[gw] = rsqrtf(fmaxf(ss, EPSV));
}

// ---------------------------------------------------------------------------
// Perspective scores: persp = S3 / (sqrt(max(S1,eps))*sqrt(max(S2,eps)))
// ---------------------------------------------------------------------------
__global__ void __launch_bounds__(128) k_persp(const float* __restrict__ inp_a,
                                               const float* __restrict__ W,
                                               float* __restrict__ out, int dup) {
    int row = blockIdx.x;
    int lane = threadIdx.x & 31;
    int w = threadIdx.x >> 5;

    const float4* a4p = (const float4*)(inp_a + (size_t)row * DD);
    const float4* h4p = (const float4*)(g_hmean + (size_t)row * DD);
    float4 a[4], h[4];
#pragma unroll
    for (int i = 0; i < 4; i++) { a[i] = a4p[lane + 32 * i]; h[i] = h4p[lane + 32 * i]; }

#pragma unroll
    for (int pp = 0; pp < 5; pp++) {
        int p = w * 5 + pp;
        const float4* w4p = (const float4*)(W + (size_t)p * DD);
        float s1 = 0.f, s2 = 0.f, s3 = 0.f;
#pragma unroll
        for (int i = 0; i < 4; i++) {
            float4 wv = w4p[lane + 32 * i];
            float w2;
            w2 = wv.x * wv.x; s1 += a[i].x * a[i].x * w2; s2 += h[i].x * h[i].x * w2; s3 += a[i].x * h[i].x * w2;
            w2 = wv.y * wv.y; s1 += a[i].y * a[i].y * w2; s2 += h[i].y * h[i].y * w2; s3 += a[i].y * h[i].y * w2;
            w2 = wv.z * wv.z; s1 += a[i].z * a[i].z * w2; s2 += h[i].z * h[i].z * w2; s3 += a[i].z * h[i].z * w2;
            w2 = wv.w * wv.w; s1 += a[i].w * a[i].w * w2; s2 += h[i].w * h[i].w * w2; s3 += a[i].w * h[i].w * w2;
        }
#pragma unroll
        for (int o = 16; o > 0; o >>= 1) {
            s1 += __shfl_xor_sync(0xffffffffu, s1, o);
            s2 += __shfl_xor_sync(0xffffffffu, s2, o);
            s3 += __shfl_xor_sync(0xffffffffu, s3, o);
        }
        if (lane == 0) {
            float v = s3 * rsqrtf(fmaxf(s1, EPSV)) * rsqrtf(fmaxf(s2, EPSV));
            out[(size_t)row * PP + p] = v;
            if (dup) out[(size_t)BB * TT * PP + (size_t)row * PP + p] = v;
        }
    }
}

// ---------------------------------------------------------------------------
extern "C" void kernel_launch(void* const* d_in, const int* in_sizes, int n_in,
                              void* d_out, int out_size) {
    const float* inp_a = (const float*)d_in[0];
    const float* inp_b = (const float*)d_in[1];
    const float* W     = (const float*)d_in[2];
    float* out = (float*)d_out;
    int dup = (out_size >= 2 * BB * TT * PP) ? 1 : 0;

    void *p_nbn, *p_nbnT, *p_nanT, *p_alphaT, *p_invcol, *p_hmean;
    cudaGetSymbolAddress(&p_nbn, g_nbn);
    cudaGetSymbolAddress(&p_nbnT, g_nbnT);
    cudaGetSymbolAddress(&p_nanT, g_nanT);
    cudaGetSymbolAddress(&p_alphaT, g_alphaT);
    cudaGetSymbolAddress(&p_invcol, g_invcol);
    cudaGetSymbolAddress(&p_hmean, g_hmean);

    // 1) normalize + transpose
    k_normT<<<dim3(TT / 16, BB, 2), 256>>>(inp_a, inp_b);

    // 2) GEMM1: alphaT[e][d] = sum_t nbnT[d,t]*nanT[e,t]  (M=512 d, N=512 e, K=256 t)
    k_gemm_mma<<<dim3(4, 4, BB), 256>>>(
        (const float*)p_nbnT, TT, (size_t)DD * TT,
        (const float*)p_nanT, TT, (size_t)DD * TT,
        (float*)p_alphaT, (size_t)DD * DD, nullptr, TT);

    // 3) inverse column norms of alpha (rows of alphaT)
    k_colnorm<<<(BB * DD) / 8, 256>>>();

    // 4) GEMM2: hmean[t][e] = (sum_d alphaT[e,d]*nbn[t,d]) * invcol[e]
    //    (M=512 e, N=256 t, K=512 d)
    k_gemm_mma<<<dim3(4, 2, BB), 256>>>(
        (const float*)p_alphaT, DD, (size_t)DD * DD,
        (const float*)p_nbn, DD, (size_t)TT * DD,
        (float*)p_hmean, (size_t)TT * DD, (const float*)p_invcol, DD);

    // 5) perspective scores
    k_persp<<<BB * TT, 128>>>(inp_a, W, out, dup);
}

// round 7
// speedup vs baseline: 1.5222x; 1.5222x over previous
#include <cuda_runtime.h>
#include <cuda_bf16.h>
#include <cstdint>

#define BB 32
#define TT 256
#define DD 512
#define PP 20
#define EPSV 1e-12f

// ---------------- scratch (__device__ globals; no cudaMalloc allowed) ------
__device__ __align__(16) __nv_bfloat16 g_nbn_bf [BB * TT * DD];   // [b][t][d]
__device__ __align__(16) __nv_bfloat16 g_nbnT_bf[BB * DD * TT];   // [b][d][t]
__device__ __align__(16) __nv_bfloat16 g_nanT_bf[BB * DD * TT];   // [b][d][t]
__device__ __align__(16) float g_alphaT[(size_t)BB * DD * DD];    // [b][e][d] fp32
__device__ __align__(16) __nv_bfloat16 g_alphaTb[(size_t)BB * DD * DD]; // bf16 copy
__device__ float g_invcol[BB * DD];                                // per (b,e)
__device__ __align__(16) float g_hmean[BB * TT * DD];              // [b][t][e]

__device__ __forceinline__ uint32_t smem_u32(const void* p) {
    return (uint32_t)__cvta_generic_to_shared(p);
}
// pack two fp32 -> bf16x2 (lo = x, hi = y), round-to-nearest-even
__device__ __forceinline__ uint32_t pack_bf2(float x, float y) {
    uint32_t r;
    asm("cvt.rn.bf16x2.f32 %0, %1, %2;" : "=r"(r) : "f"(y), "f"(x));
    return r;
}

// ---------------------------------------------------------------------------
// Kernel 1: row l2-normalize + transpose, bf16 outputs.
// which=0: a -> g_nanT_bf.  which=1: b -> g_nbn_bf + g_nbnT_bf.
// ---------------------------------------------------------------------------
__global__ void __launch_bounds__(256) k_normT(const float* __restrict__ a,
                                               const float* __restrict__ b) {
    __shared__ float s[16 * 513];
    __shared__ float sinv[16];
    int which = blockIdx.z;
    int bb = blockIdx.y;
    int t0 = blockIdx.x * 16;
    const float* src = (which ? b : a) + ((size_t)bb * TT + t0) * DD;
    int tid = threadIdx.x;

#pragma unroll
    for (int i = 0; i < 8; i++) {
        int idx = tid + i * 256;
        int r = idx >> 7, c4 = idx & 127;
        float4 v = *(const float4*)(src + (size_t)r * DD + c4 * 4);
        float* sr = s + r * 513 + c4 * 4;
        sr[0] = v.x; sr[1] = v.y; sr[2] = v.z; sr[3] = v.w;
    }
    __syncthreads();

    int wid = tid >> 5, lid = tid & 31;
#pragma unroll
    for (int rr = 0; rr < 2; rr++) {
        int r = wid * 2 + rr;
        float ss = 0.f;
#pragma unroll
        for (int j = 0; j < 16; j++) { float v = s[r * 513 + lid + 32 * j]; ss += v * v; }
#pragma unroll
        for (int o = 16; o > 0; o >>= 1) ss += __shfl_xor_sync(0xffffffffu, ss, o);
        if (lid == 0) sinv[r] = rsqrtf(fmaxf(ss, EPSV));
    }
    __syncthreads();

    // transposed bf16 write: nT[d][t0+j]
    __nv_bfloat16* dstT = (which ? g_nbnT_bf : g_nanT_bf) + (size_t)bb * DD * TT;
#pragma unroll
    for (int i = 0; i < 8; i++) {
        int idx = tid + i * 256;          // over 512 d x 4 t-quads
        int d = idx >> 2, jq = (idx & 3) * 4;
        float o0 = s[(jq + 0) * 513 + d] * sinv[jq + 0];
        float o1 = s[(jq + 1) * 513 + d] * sinv[jq + 1];
        float o2 = s[(jq + 2) * 513 + d] * sinv[jq + 2];
        float o3 = s[(jq + 3) * 513 + d] * sinv[jq + 3];
        uint2 u = make_uint2(pack_bf2(o0, o1), pack_bf2(o2, o3));
        *(uint2*)(dstT + (size_t)d * TT + t0 + jq) = u;
    }
    if (which) {
        __nv_bfloat16* dst = g_nbn_bf + ((size_t)bb * TT + t0) * DD;
#pragma unroll
        for (int i = 0; i < 8; i++) {
            int idx = tid + i * 256;
            int r = idx >> 7, c4 = idx & 127;
            float inv = sinv[r];
            float* sr = s + r * 513 + c4 * 4;
            uint2 u = make_uint2(pack_bf2(sr[0] * inv, sr[1] * inv),
                                 pack_bf2(sr[2] * inv, sr[3] * inv));
            *(uint2*)(dst + (size_t)r * DD + c4 * 4) = u;
        }
    }
}

// ---------------------------------------------------------------------------
// bf16 mma.sync GEMM, 3-stage cp.async pipeline, ldmatrix fragment loads.
// D[m,n] = sum_k A[m,k]*B[n,k], both K-major bf16. CTA tile 128x128,
// K-chunk 32 (A/B stage 8KB each). Swizzle: 16B quad q -> q ^ ((r>>1)&3).
// Store transposed: C[n*512 + m] fp32, optional per-m scale.
// ---------------------------------------------------------------------------
__global__ void __launch_bounds__(256, 2) k_gemm_bf16(
    const __nv_bfloat16* __restrict__ Ag, int lda, size_t strideA,
    const __nv_bfloat16* __restrict__ Bg, int ldb, size_t strideB,
    float* __restrict__ Cg, size_t strideC,
    const float* __restrict__ scale,   // [BB*DD] indexed by m, or null
    int Ktot) {
    __shared__ __align__(16) char sm[3 * 16384];  // 48KB: 3 x (A 8KB + B 8KB)

    int b = blockIdx.z;
    int m0 = blockIdx.x * 128, n0 = blockIdx.y * 128;
    const __nv_bfloat16* A  = Ag + (size_t)b * strideA + (size_t)m0 * lda;
    const __nv_bfloat16* Bp = Bg + (size_t)b * strideB + (size_t)n0 * ldb;

    int tid = threadIdx.x, lane = tid & 31, wid = tid >> 5;
    int wm = wid & 1, wn = wid >> 1;   // 2 x 4 warp grid, warp tile 64x32
    uint32_t smbase = smem_u32(sm);

    float acc[4][4][4];
#pragma unroll
    for (int i = 0; i < 4; i++)
#pragma unroll
        for (int j = 0; j < 4; j++)
#pragma unroll
            for (int k = 0; k < 4; k++) acc[i][j][k] = 0.f;

    int nkt = Ktot / 32;

    auto issue_chunk = [&](int kt) {
        uint32_t base = smbase + (uint32_t)(kt % 3) * 16384u;
        int k0 = kt * 32;
#pragma unroll
        for (int i = 0; i < 2; i++) {
            int idx = tid + i * 256;
            int r = idx >> 2, q = idx & 3;
            uint32_t off = (uint32_t)(r * 64 + ((q ^ ((r >> 1) & 3)) << 4));
            const __nv_bfloat16* srcA = A + (size_t)r * lda + k0 + q * 8;
            asm volatile("cp.async.cg.shared.global [%0], [%1], 16;"
                         :: "r"(base + off), "l"(srcA));
            const __nv_bfloat16* srcB = Bp + (size_t)r * ldb + k0 + q * 8;
            asm volatile("cp.async.cg.shared.global [%0], [%1], 16;"
                         :: "r"(base + 8192u + off), "l"(srcB));
        }
        asm volatile("cp.async.commit_group;");
    };

    issue_chunk(0);
    if (nkt > 1) issue_chunk(1);

    for (int kt = 0; kt < nkt; kt++) {
        asm volatile("cp.async.wait_group 1;" ::: "memory");
        __syncthreads();
        if (kt + 2 < nkt) issue_chunk(kt + 2);

        uint32_t baseA = smbase + (uint32_t)(kt % 3) * 16384u;
        uint32_t baseB = baseA + 8192u;

#pragma unroll
        for (int ks = 0; ks < 2; ks++) {
            uint32_t af[4][4], bf[4][2];
#pragma unroll
            for (int mt = 0; mt < 4; mt++) {
                int r = wm * 64 + mt * 16 + (lane & 15);
                int q = ks * 2 + (lane >> 4);
                uint32_t addr = baseA + (uint32_t)(r * 64 + ((q ^ ((r >> 1) & 3)) << 4));
                asm volatile("ldmatrix.sync.aligned.m8n8.x4.shared.b16 {%0,%1,%2,%3}, [%4];"
                             : "=r"(af[mt][0]), "=r"(af[mt][1]),
                               "=r"(af[mt][2]), "=r"(af[mt][3])
                             : "r"(addr));
            }
#pragma unroll
            for (int nt = 0; nt < 4; nt++) {
                int r = wn * 32 + nt * 8 + (lane & 7);
                int q = ks * 2 + ((lane >> 3) & 1);
                uint32_t addr = baseB + (uint32_t)(r * 64 + ((q ^ ((r >> 1) & 3)) << 4));
                asm volatile("ldmatrix.sync.aligned.m8n8.x2.shared.b16 {%0,%1}, [%2];"
                             : "=r"(bf[nt][0]), "=r"(bf[nt][1])
                             : "r"(addr));
            }
#pragma unroll
            for (int mt = 0; mt < 4; mt++)
#pragma unroll
                for (int nt = 0; nt < 4; nt++) {
                    asm volatile(
                        "mma.sync.aligned.m16n8k16.row.col.f32.bf16.bf16.f32 "
                        "{%0,%1,%2,%3}, {%4,%5,%6,%7}, {%8,%9}, {%0,%1,%2,%3};"
                        : "+f"(acc[mt][nt][0]), "+f"(acc[mt][nt][1]),
                          "+f"(acc[mt][nt][2]), "+f"(acc[mt][nt][3])
                        : "r"(af[mt][0]), "r"(af[mt][1]),
                          "r"(af[mt][2]), "r"(af[mt][3]),
                          "r"(bf[nt][0]), "r"(bf[nt][1]));
                }
        }
        __syncthreads();
    }

    // ---- epilogue: transposed store C[n*512 + m] fp32, optional scale[m] ----
    float* Cb = Cg + (size_t)b * strideC;
    const float* scb = scale ? (scale + (size_t)b * DD) : nullptr;
#pragma unroll
    for (int mt = 0; mt < 4; mt++) {
        int r0 = m0 + wm * 64 + mt * 16 + (lane >> 2);
        float sc0 = scb ? scb[r0] : 1.0f;
        float sc1 = scb ? scb[r0 + 8] : 1.0f;
#pragma unroll
        for (int nt = 0; nt < 4; nt++) {
            int c0 = n0 + wn * 32 + nt * 8 + (lane & 3) * 2;
            Cb[(size_t)c0 * 512 + r0]           = acc[mt][nt][0] * sc0;
            Cb[(size_t)(c0 + 1) * 512 + r0]     = acc[mt][nt][1] * sc0;
            Cb[(size_t)c0 * 512 + r0 + 8]       = acc[mt][nt][2] * sc1;
            Cb[(size_t)(c0 + 1) * 512 + r0 + 8] = acc[mt][nt][3] * sc1;
        }
    }
}

// ---------------------------------------------------------------------------
// Column norms of alpha (rows of alphaT) + bf16 conversion of alphaT.
// One warp per (b,e) row.
// ---------------------------------------------------------------------------
__global__ void __launch_bounds__(256) k_colnorm() {
    int gw = (blockIdx.x * blockDim.x + threadIdx.x) >> 5;
    int lane = threadIdx.x & 31;
    if (gw >= BB * DD) return;
    const float4* r4 = (const float4*)(g_alphaT + (size_t)gw * DD);
    __nv_bfloat16* ob = g_alphaTb + (size_t)gw * DD;
    float ss = 0.f;
#pragma unroll
    for (int i = 0; i < 4; i++) {
        float4 v = r4[lane + 32 * i];
        ss += v.x * v.x + v.y * v.y + v.z * v.z + v.w * v.w;
        uint2 u = make_uint2(pack_bf2(v.x, v.y), pack_bf2(v.z, v.w));
        *(uint2*)(ob + (size_t)(lane + 32 * i) * 4) = u;
    }
#pragma unroll
    for (int o = 16; o > 0; o >>= 1) ss += __shfl_xor_sync(0xffffffffu, ss, o);
    if (lane == 0) g_invcol[gw] = rsqrtf(fmaxf(ss, EPSV));
}

// ---------------------------------------------------------------------------
// Perspective scores: persp = S3 / (sqrt(max(S1,eps))*sqrt(max(S2,eps)))
// ---------------------------------------------------------------------------
__global__ void __launch_bounds__(128) k_persp(const float* __restrict__ inp_a,
                                               const float* __restrict__ W,
                                               float* __restrict__ out, int dup) {
    int row = blockIdx.x;
    int lane = threadIdx.x & 31;
    int w = threadIdx.x >> 5;

    const float4* a4p = (const float4*)(inp_a + (size_t)row * DD);
    const float4* h4p = (const float4*)(g_hmean + (size_t)row * DD);
    float4 a[4], h[4];
#pragma unroll
    for (int i = 0; i < 4; i++) { a[i] = a4p[lane + 32 * i]; h[i] = h4p[lane + 32 * i]; }

#pragma unroll
    for (int pp = 0; pp < 5; pp++) {
        int p = w * 5 + pp;
        const float4* w4p = (const float4*)(W + (size_t)p * DD);
        float s1 = 0.f, s2 = 0.f, s3 = 0.f;
#pragma unroll
        for (int i = 0; i < 4; i++) {
            float4 wv = w4p[lane + 32 * i];
            float w2;
            w2 = wv.x * wv.x; s1 += a[i].x * a[i].x * w2; s2 += h[i].x * h[i].x * w2; s3 += a[i].x * h[i].x * w2;
            w2 = wv.y * wv.y; s1 += a[i].y * a[i].y * w2; s2 += h[i].y * h[i].y * w2; s3 += a[i].y * h[i].y * w2;
            w2 = wv.z * wv.z; s1 += a[i].z * a[i].z * w2; s2 += h[i].z * h[i].z * w2; s3 += a[i].z * h[i].z * w2;
            w2 = wv.w * wv.w; s1 += a[i].w * a[i].w * w2; s2 += h[i].w * h[i].w * w2; s3 += a[i].w * h[i].w * w2;
        }
#pragma unroll
        for (int o = 16; o > 0; o >>= 1) {
            s1 += __shfl_xor_sync(0xffffffffu, s1, o);
            s2 += __shfl_xor_sync(0xffffffffu, s2, o);
            s3 += __shfl_xor_sync(0xffffffffu, s3, o);
        }
        if (lane == 0) {
            float v = s3 * rsqrtf(fmaxf(s1, EPSV)) * rsqrtf(fmaxf(s2, EPSV));
            out[(size_t)row * PP + p] = v;
            if (dup) out[(size_t)BB * TT * PP + (size_t)row * PP + p] = v;
        }
    }
}

// ---------------------------------------------------------------------------
extern "C" void kernel_launch(void* const* d_in, const int* in_sizes, int n_in,
                              void* d_out, int out_size) {
    const float* inp_a = (const float*)d_in[0];
    const float* inp_b = (const float*)d_in[1];
    const float* W     = (const float*)d_in[2];
    float* out = (float*)d_out;
    int dup = (out_size >= 2 * BB * TT * PP) ? 1 : 0;

    void *p_nbn_bf, *p_nbnT_bf, *p_nanT_bf, *p_alphaT, *p_alphaTb, *p_invcol, *p_hmean;
    cudaGetSymbolAddress(&p_nbn_bf, g_nbn_bf);
    cudaGetSymbolAddress(&p_nbnT_bf, g_nbnT_bf);
    cudaGetSymbolAddress(&p_nanT_bf, g_nanT_bf);
    cudaGetSymbolAddress(&p_alphaT, g_alphaT);
    cudaGetSymbolAddress(&p_alphaTb, g_alphaTb);
    cudaGetSymbolAddress(&p_invcol, g_invcol);
    cudaGetSymbolAddress(&p_hmean, g_hmean);

    // 1) normalize + transpose -> bf16
    k_normT<<<dim3(TT / 16, BB, 2), 256>>>(inp_a, inp_b);

    // 2) GEMM1: alphaT[e][d] = sum_t nbnT[d,t]*nanT[e,t]  (M=512 d, N=512 e, K=256 t)
    k_gemm_bf16<<<dim3(4, 4, BB), 256>>>(
        (const __nv_bfloat16*)p_nbnT_bf, TT, (size_t)DD * TT,
        (const __nv_bfloat16*)p_nanT_bf, TT, (size_t)DD * TT,
        (float*)p_alphaT, (size_t)DD * DD, nullptr, TT);

    // 3) inverse column norms of alpha + bf16 copy of alphaT
    k_colnorm<<<(BB * DD) / 8, 256>>>();

    // 4) GEMM2: hmean[t][e] = (sum_d alphaTb[e,d]*nbn[t,d]) * invcol[e]
    //    (M=512 e, N=256 t, K=512 d)
    k_gemm_bf16<<<dim3(4, 2, BB), 256>>>(
        (const __nv_bfloat16*)p_alphaTb, DD, (size_t)DD * DD,
        (const __nv_bfloat16*)p_nbn_bf, DD, (size_t)TT * DD,
        (float*)p_hmean, (size_t)TT * DD, (const float*)p_invcol, DD);

    // 5) perspective scores
    k_persp<<<BB * TT, 128>>>(inp_a, W, out, dup);
}